// round 15
// baseline (speedup 1.0000x reference)
#include <cuda_runtime.h>
#include <math_constants.h>

// Dims
#define S_DIM 256
#define L_DIM 256
#define CMD   256
#define CZD   128
#define NH    8
#define CHD   32
#define ROWS  (S_DIM*L_DIM)   // 65536

// ---------------- scratch (device globals; no allocation allowed) ----------
__device__ float d_mu[ROWS];
__device__ float d_rs[ROWS];
__device__ float d_q [ROWS*CMD];   // [L][H][S][CHD], q pre-scaled by 1/sqrt(32)
__device__ float d_kk[ROWS*CMD];   // [L][H][S][CHD]
__device__ float d_v [ROWS*CMD];   // [L][H][S][CHD]
__device__ float d_g [ROWS*CMD];   // [S*L][256]  sigmoid gate
__device__ float d_bias[NH*S_DIM*S_DIM]; // [h][s][t]
__device__ float d_o [ROWS*CMD];   // [S][L][H*CHD]

typedef unsigned long long u64;

__device__ __forceinline__ u64 ffma2(u64 a, u64 b, u64 c) {
    u64 d; asm("fma.rn.f32x2 %0, %1, %2, %3;" : "=l"(d) : "l"(a), "l"(b), "l"(c)); return d;
}
__device__ __forceinline__ u64 fmul2(u64 a, u64 b) {
    u64 d; asm("mul.rn.f32x2 %0, %1, %2;" : "=l"(d) : "l"(a), "l"(b)); return d;
}
__device__ __forceinline__ u64 pack2(float x, float y) {
    u64 r; asm("mov.b64 %0, {%1, %2};" : "=l"(r) : "f"(x), "f"(y)); return r;
}
__device__ __forceinline__ float2 unpack2(u64 v) {
    float2 r; asm("mov.b64 {%0, %1}, %2;" : "=f"(r.x), "=f"(r.y) : "l"(v)); return r;
}

// ---------------- K1: per-row mean / rsqrt(var) of m -----------------------
__global__ __launch_bounds__(256) void ln_stats_kernel(const float* __restrict__ m) {
    int row  = blockIdx.x * 8 + (threadIdx.x >> 5);
    int lane = threadIdx.x & 31;
    const float4* p = reinterpret_cast<const float4*>(m + row * CMD);
    float4 a = p[lane * 2];
    float4 b = p[lane * 2 + 1];
    float s  = a.x + a.y + a.z + a.w + b.x + b.y + b.z + b.w;
    float s2 = a.x*a.x + a.y*a.y + a.z*a.z + a.w*a.w
             + b.x*b.x + b.y*b.y + b.z*b.z + b.w*b.w;
    #pragma unroll
    for (int off = 16; off; off >>= 1) {
        s  += __shfl_xor_sync(0xffffffffu, s,  off);
        s2 += __shfl_xor_sync(0xffffffffu, s2, off);
    }
    if (lane == 0) {
        float mu  = s  * (1.0f / CMD);
        float var = s2 * (1.0f / CMD) - mu * mu;
        d_mu[row] = mu;
        d_rs[row] = rsqrtf(var + 1e-5f);
    }
}

// ---------------- K2: LN(z) fused with pair-bias projection ----------------
// bias[h][i][j] = sum_c LN(z[i,j,c]) * Wb[c][h]   (independent of l)
__global__ __launch_bounds__(256) void zbias_kernel(const float* __restrict__ z,
                                                    const float* __restrict__ g_z,
                                                    const float* __restrict__ b_z,
                                                    const float* __restrict__ Wb) {
    __shared__ float sWb[CZD * 9];  // stride 9 to kill bank conflicts
    __shared__ float sgz[CZD], sbz[CZD];
    for (int i = threadIdx.x; i < CZD * NH; i += 256)
        sWb[(i >> 3) * 9 + (i & 7)] = Wb[i];
    for (int i = threadIdx.x; i < CZD; i += 256) { sgz[i] = g_z[i]; sbz[i] = b_z[i]; }
    __syncthreads();

    int row  = blockIdx.x * 8 + (threadIdx.x >> 5);
    int lane = threadIdx.x & 31;
    float4 x = reinterpret_cast<const float4*>(z + row * CZD)[lane];
    float s  = x.x + x.y + x.z + x.w;
    float s2 = x.x*x.x + x.y*x.y + x.z*x.z + x.w*x.w;
    #pragma unroll
    for (int off = 16; off; off >>= 1) {
        s  += __shfl_xor_sync(0xffffffffu, s,  off);
        s2 += __shfl_xor_sync(0xffffffffu, s2, off);
    }
    float mu = s * (1.0f / CZD);
    float rs = rsqrtf(s2 * (1.0f / CZD) - mu * mu + 1e-5f);
    int c0 = lane * 4;
    float xl0 = (x.x - mu) * rs * sgz[c0 + 0] + sbz[c0 + 0];
    float xl1 = (x.y - mu) * rs * sgz[c0 + 1] + sbz[c0 + 1];
    float xl2 = (x.z - mu) * rs * sgz[c0 + 2] + sbz[c0 + 2];
    float xl3 = (x.w - mu) * rs * sgz[c0 + 3] + sbz[c0 + 3];
    float p8[NH];
    #pragma unroll
    for (int h = 0; h < NH; h++) {
        p8[h] = xl0 * sWb[(c0 + 0) * 9 + h] + xl1 * sWb[(c0 + 1) * 9 + h]
              + xl2 * sWb[(c0 + 2) * 9 + h] + xl3 * sWb[(c0 + 3) * 9 + h];
    }
    #pragma unroll
    for (int off = 16; off; off >>= 1) {
        #pragma unroll
        for (int h = 0; h < NH; h++)
            p8[h] += __shfl_xor_sync(0xffffffffu, p8[h], off);
    }
    if (lane == 0) {
        #pragma unroll
        for (int h = 0; h < NH; h++)
            d_bias[h * (S_DIM * S_DIM) + row] = p8[h];
    }
}

// ---------------- K3: fused-LN projection GEMM (Q,K,V,Gate) ----------------
// C[65536 x 1024] = LN(m) @ [Wq | Wk | Wv | Wg]; epilogue routes per group.
__global__ __launch_bounds__(256, 2) void proj_kernel(const float* __restrict__ m,
                                                      const float* __restrict__ g_m,
                                                      const float* __restrict__ b_m,
                                                      const float* __restrict__ Wq,
                                                      const float* __restrict__ Wk,
                                                      const float* __restrict__ Wv,
                                                      const float* __restrict__ Wg,
                                                      const float* __restrict__ bg) {
    __shared__ float As[16 * 132];
    __shared__ float Bs[16 * 128];
    __shared__ float smu[128], srs[128];
    int tid = threadIdx.x;
    int m0  = blockIdx.y * 128;
    int bw  = blockIdx.x;            // 0..7
    int w   = bw >> 1;               // 0=q 1=k 2=v 3=g
    int nn0 = (bw & 1) * 128;        // column offset inside W
    const float* W = (w == 0) ? Wq : (w == 1) ? Wk : (w == 2) ? Wv : Wg;

    if (tid < 128) { smu[tid] = d_mu[m0 + tid]; srs[tid] = d_rs[m0 + tid]; }
    __syncthreads();

    u64 acc[8][4];
    #pragma unroll
    for (int i = 0; i < 8; i++)
        #pragma unroll
        for (int j = 0; j < 4; j++) acc[i][j] = 0ull;

    int tx = tid & 15, ty = tid >> 4;

    for (int kt = 0; kt < 16; kt++) {
        int k0 = kt * 16;
        #pragma unroll
        for (int ii = 0; ii < 2; ii++) {   // A tile (LN applied on load)
            int slot = tid + ii * 256;
            int ra = slot >> 2, c4 = slot & 3;
            int kA = k0 + c4 * 4;
            float4 x  = *reinterpret_cast<const float4*>(m + (m0 + ra) * CMD + kA);
            float mu = smu[ra], rs = srs[ra];
            float4 gv = *reinterpret_cast<const float4*>(g_m + kA);
            float4 bv = *reinterpret_cast<const float4*>(b_m + kA);
            As[(c4 * 4 + 0) * 132 + ra] = (x.x - mu) * rs * gv.x + bv.x;
            As[(c4 * 4 + 1) * 132 + ra] = (x.y - mu) * rs * gv.y + bv.y;
            As[(c4 * 4 + 2) * 132 + ra] = (x.z - mu) * rs * gv.z + bv.z;
            As[(c4 * 4 + 3) * 132 + ra] = (x.w - mu) * rs * gv.w + bv.w;
        }
        #pragma unroll
        for (int ii = 0; ii < 2; ii++) {   // B tile
            int slot = tid + ii * 256;
            int kk = slot >> 5, c4 = slot & 31;
            *reinterpret_cast<float4*>(&Bs[kk * 128 + c4 * 4]) =
                *reinterpret_cast<const float4*>(W + (k0 + kk) * 256 + nn0 + c4 * 4);
        }
        __syncthreads();
        #pragma unroll
        for (int kk = 0; kk < 16; kk++) {
            float4 a0 = *reinterpret_cast<const float4*>(&As[kk * 132 + ty * 8]);
            float4 a1 = *reinterpret_cast<const float4*>(&As[kk * 132 + ty * 8 + 4]);
            ulonglong2 b0 = *reinterpret_cast<const ulonglong2*>(&Bs[kk * 128 + tx * 8]);
            ulonglong2 b1 = *reinterpret_cast<const ulonglong2*>(&Bs[kk * 128 + tx * 8 + 4]);
            float av[8] = {a0.x, a0.y, a0.z, a0.w, a1.x, a1.y, a1.z, a1.w};
            #pragma unroll
            for (int i = 0; i < 8; i++) {
                u64 a2 = pack2(av[i], av[i]);
                acc[i][0] = ffma2(a2, b0.x, acc[i][0]);
                acc[i][1] = ffma2(a2, b0.y, acc[i][1]);
                acc[i][2] = ffma2(a2, b1.x, acc[i][2]);
                acc[i][3] = ffma2(a2, b1.y, acc[i][3]);
            }
        }
        __syncthreads();
    }

    // ---- epilogue ----
    int ncol0 = nn0 + tx * 8;  // 0..248 within this W
    if (w == 3) {
        float4 bg0 = *reinterpret_cast<const float4*>(bg + ncol0);
        float4 bg1 = *reinterpret_cast<const float4*>(bg + ncol0 + 4);
        float bgv[8] = {bg0.x, bg0.y, bg0.z, bg0.w, bg1.x, bg1.y, bg1.z, bg1.w};
        #pragma unroll
        for (int i = 0; i < 8; i++) {
            int r = m0 + ty * 8 + i;
            float out[8];
            #pragma unroll
            for (int j2 = 0; j2 < 4; j2++) {
                float2 u = unpack2(acc[i][j2]);
                out[2 * j2] = u.x; out[2 * j2 + 1] = u.y;
            }
            #pragma unroll
            for (int j = 0; j < 8; j++)
                out[j] = 1.0f / (1.0f + __expf(-(out[j] + bgv[j])));
            float* dst = d_g + r * CMD + ncol0;
            *reinterpret_cast<float4*>(dst)     = make_float4(out[0], out[1], out[2], out[3]);
            *reinterpret_cast<float4*>(dst + 4) = make_float4(out[4], out[5], out[6], out[7]);
        }
    } else {
        float scale = (w == 0) ? 0.17677669529663687f : 1.0f;  // 1/sqrt(32) folded into q
        int h  = ncol0 >> 5, c0 = ncol0 & 31;
        float* base = (w == 0) ? d_q : (w == 1) ? d_kk : d_v;
        #pragma unroll
        for (int i = 0; i < 8; i++) {
            int r = m0 + ty * 8 + i;
            int s = r >> 8, l = r & 255;
            float out[8];
            #pragma unroll
            for (int j2 = 0; j2 < 4; j2++) {
                float2 u = unpack2(acc[i][j2]);
                out[2 * j2] = u.x * scale; out[2 * j2 + 1] = u.y * scale;
            }
            float* dst = base + ((l * NH + h) * S_DIM + s) * CHD + c0;
            *reinterpret_cast<float4*>(dst)     = make_float4(out[0], out[1], out[2], out[3]);
            *reinterpret_cast<float4*>(dst + 4) = make_float4(out[4], out[5], out[6], out[7]);
        }
    }
}

// ---------------- K4: attention per (l,h), online softmax ------------------
__global__ __launch_bounds__(256) void attn_kernel() {
    extern __shared__ __align__(16) float sh[];
    float* ks = sh;          // [256][32]
    float* vs = sh + 8192;   // [256][32]
    int l = blockIdx.x >> 3;
    int h = blockIdx.x & 7;
    int base = (l * NH + h) * (S_DIM * CHD);

    const float4* kg = reinterpret_cast<const float4*>(d_kk + base);
    const float4* vg = reinterpret_cast<const float4*>(d_v  + base);
    for (int idx = threadIdx.x; idx < 2048; idx += 256) {
        reinterpret_cast<float4*>(ks)[idx] = kg[idx];
        reinterpret_cast<float4*>(vs)[idx] = vg[idx];
    }
    int s = threadIdx.x;
    u64 q2[16];
    {
        const ulonglong2* qp = reinterpret_cast<const ulonglong2*>(d_q + base + s * CHD);
        #pragma unroll
        for (int i = 0; i < 8; i++) { ulonglong2 t = qp[i]; q2[2 * i] = t.x; q2[2 * i + 1] = t.y; }
    }
    __syncthreads();

    float mrun = -CUDART_INF_F;
    float lrun = 0.0f;
    u64 o2[16];
    #pragma unroll
    for (int c = 0; c < 16; c++) o2[c] = 0ull;

    const float4* bp = reinterpret_cast<const float4*>(d_bias + h * (S_DIM * S_DIM) + s * S_DIM);

    #pragma unroll 1
    for (int tt = 0; tt < 8; tt++) {
        float ch[32];
        #pragma unroll
        for (int j4 = 0; j4 < 8; j4++) {
            float4 b4 = bp[tt * 8 + j4];
            ch[j4 * 4 + 0] = b4.x; ch[j4 * 4 + 1] = b4.y;
            ch[j4 * 4 + 2] = b4.z; ch[j4 * 4 + 3] = b4.w;
        }
        #pragma unroll
        for (int j = 0; j < 32; j++) {
            const ulonglong2* kp = reinterpret_cast<const ulonglong2*>(ks + (tt * 32 + j) * CHD);
            u64 accA = 0ull, accB = 0ull;
            #pragma unroll
            for (int c = 0; c < 8; c++) {
                ulonglong2 kv = kp[c];
                accA = ffma2(q2[2 * c],     kv.x, accA);
                accB = ffma2(q2[2 * c + 1], kv.y, accB);
            }
            float2 ua = unpack2(accA);
            float2 ub = unpack2(accB);
            ch[j] += (ua.x + ua.y) + (ub.x + ub.y);
        }
        float tmax = mrun;
        #pragma unroll
        for (int j = 0; j < 32; j++) tmax = fmaxf(tmax, ch[j]);
        float sc = __expf(mrun - tmax);  // 0 on first tile (mrun = -inf)
        mrun = tmax;
        lrun *= sc;
        u64 sc2 = pack2(sc, sc);
        #pragma unroll
        for (int c = 0; c < 16; c++) o2[c] = fmul2(o2[c], sc2);
        #pragma unroll
        for (int j = 0; j < 32; j++) {
            float e = __expf(ch[j] - tmax);
            lrun += e;
            u64 e2 = pack2(e, e);
            const ulonglong2* vp = reinterpret_cast<const ulonglong2*>(vs + (tt * 32 + j) * CHD);
            #pragma unroll
            for (int c = 0; c < 8; c++) {
                ulonglong2 vv = vp[c];
                o2[2 * c]     = ffma2(e2, vv.x, o2[2 * c]);
                o2[2 * c + 1] = ffma2(e2, vv.y, o2[2 * c + 1]);
            }
        }
    }
    float inv = 1.0f / lrun;
    float out[32];
    #pragma unroll
    for (int c = 0; c < 16; c++) {
        float2 u = unpack2(o2[c]);
        out[2 * c] = u.x * inv; out[2 * c + 1] = u.y * inv;
    }
    float* dst = d_o + (s * L_DIM + l) * CMD + h * CHD;
    #pragma unroll
    for (int c4 = 0; c4 < 8; c4++)
        reinterpret_cast<float4*>(dst)[c4] =
            make_float4(out[4 * c4], out[4 * c4 + 1], out[4 * c4 + 2], out[4 * c4 + 3]);
}

// ---------------- K5: output GEMM (gate fused on A load) -------------------
__global__ __launch_bounds__(256, 2) void out_kernel(const float* __restrict__ Wo,
                                                     const float* __restrict__ bo,
                                                     float* __restrict__ outp) {
    __shared__ float As[16 * 132];
    __shared__ float Bs[16 * 128];
    int tid = threadIdx.x;
    int m0 = blockIdx.y * 128;
    int n0 = blockIdx.x * 128;

    u64 acc[8][4];
    #pragma unroll
    for (int i = 0; i < 8; i++)
        #pragma unroll
        for (int j = 0; j < 4; j++) acc[i][j] = 0ull;

    int tx = tid & 15, ty = tid >> 4;

    for (int kt = 0; kt < 16; kt++) {
        int k0 = kt * 16;
        #pragma unroll
        for (int ii = 0; ii < 2; ii++) {
            int slot = tid + ii * 256;
            int ra = slot >> 2, c4 = slot & 3;
            int kA = k0 + c4 * 4;
            float4 gv = *reinterpret_cast<const float4*>(d_g + (m0 + ra) * CMD + kA);
            float4 ov = *reinterpret_cast<const float4*>(d_o + (m0 + ra) * CMD + kA);
            As[(c4 * 4 + 0) * 132 + ra] = gv.x * ov.x;
            As[(c4 * 4 + 1) * 132 + ra] = gv.y * ov.y;
            As[(c4 * 4 + 2) * 132 + ra] = gv.z * ov.z;
            As[(c4 * 4 + 3) * 132 + ra] = gv.w * ov.w;
        }
        #pragma unroll
        for (int ii = 0; ii < 2; ii++) {
            int slot = tid + ii * 256;
            int kk = slot >> 5, c4 = slot & 31;
            *reinterpret_cast<float4*>(&Bs[kk * 128 + c4 * 4]) =
                *reinterpret_cast<const float4*>(Wo + (k0 + kk) * 256 + n0 + c4 * 4);
        }
        __syncthreads();
        #pragma unroll
        for (int kk = 0; kk < 16; kk++) {
            float4 a0 = *reinterpret_cast<const float4*>(&As[kk * 132 + ty * 8]);
            float4 a1 = *reinterpret_cast<const float4*>(&As[kk * 132 + ty * 8 + 4]);
            ulonglong2 b0 = *reinterpret_cast<const ulonglong2*>(&Bs[kk * 128 + tx * 8]);
            ulonglong2 b1 = *reinterpret_cast<const ulonglong2*>(&Bs[kk * 128 + tx * 8 + 4]);
            float av[8] = {a0.x, a0.y, a0.z, a0.w, a1.x, a1.y, a1.z, a1.w};
            #pragma unroll
            for (int i = 0; i < 8; i++) {
                u64 a2 = pack2(av[i], av[i]);
                acc[i][0] = ffma2(a2, b0.x, acc[i][0]);
                acc[i][1] = ffma2(a2, b0.y, acc[i][1]);
                acc[i][2] = ffma2(a2, b1.x, acc[i][2]);
                acc[i][3] = ffma2(a2, b1.y, acc[i][3]);
            }
        }
        __syncthreads();
    }

    int ncol0 = n0 + tx * 8;
    float4 bo0 = *reinterpret_cast<const float4*>(bo + ncol0);
    float4 bo1 = *reinterpret_cast<const float4*>(bo + ncol0 + 4);
    float bov[8] = {bo0.x, bo0.y, bo0.z, bo0.w, bo1.x, bo1.y, bo1.z, bo1.w};
    #pragma unroll
    for (int i = 0; i < 8; i++) {
        int r = m0 + ty * 8 + i;
        float out[8];
        #pragma unroll
        for (int j2 = 0; j2 < 4; j2++) {
            float2 u = unpack2(acc[i][j2]);
            out[2 * j2] = u.x + bov[2 * j2];
            out[2 * j2 + 1] = u.y + bov[2 * j2 + 1];
        }
        float* dst = outp + r * CMD + ncol0;
        *reinterpret_cast<float4*>(dst)     = make_float4(out[0], out[1], out[2], out[3]);
        *reinterpret_cast<float4*>(dst + 4) = make_float4(out[4], out[5], out[6], out[7]);
    }
}

// ---------------- launch ----------------------------------------------------
extern "C" void kernel_launch(void* const* d_in, const int* in_sizes, int n_in,
                              void* d_out, int out_size) {
    const float* m   = (const float*)d_in[0];
    const float* z   = (const float*)d_in[1];
    const float* g_m = (const float*)d_in[2];
    const float* b_m = (const float*)d_in[3];
    const float* g_z = (const float*)d_in[4];
    const float* b_z = (const float*)d_in[5];
    const float* Wq  = (const float*)d_in[6];
    const float* Wk  = (const float*)d_in[7];
    const float* Wv  = (const float*)d_in[8];
    const float* Wb  = (const float*)d_in[9];
    const float* Wg  = (const float*)d_in[10];
    const float* bg  = (const float*)d_in[11];
    const float* Wo  = (const float*)d_in[12];
    const float* bo  = (const float*)d_in[13];

    cudaFuncSetAttribute(attn_kernel, cudaFuncAttributeMaxDynamicSharedMemorySize, 65536);

    ln_stats_kernel<<<ROWS / 8, 256>>>(m);
    zbias_kernel<<<(L_DIM * L_DIM) / 8, 256>>>(z, g_z, b_z, Wb);
    proj_kernel<<<dim3(8, ROWS / 128), 256>>>(m, g_m, b_m, Wq, Wk, Wv, Wg, bg);
    attn_kernel<<<L_DIM * NH, 256, 65536>>>();
    out_kernel<<<dim3(2, ROWS / 128), 256>>>(Wo, bo, (float*)d_out);
}